// round 17
// baseline (speedup 1.0000x reference)
#include <cuda_runtime.h>
#include <cstdint>

// Problem constants
#define BATCH 1024
#define SEQ   512
#define NF    64
#define H     128
#define G4    512
#define NOUT  128

// Kernel config
#define M     8
#define NCTA  128
#define NTHR  1024
#define KX    16               // x-rows per kgroup (resident)
#define KH    32               // h-rows per kgroup (all streamed)

// smem layout (floats)
#define OFF_WIH   0                        // [64][512]
#define OFF_XD    (NF * G4)                // [2][64][8]
#define OFF_HD    (OFF_XD + 2 * NF * M)    // [128][8]
#define OFF_PART  (OFF_HD + H * M)         // [4][8][512] raw gate partials
#define SMEM_FLOATS (OFF_PART + 4 * 8 * G4)   // 51200
#define SMEM_BYTES  (SMEM_FLOATS * 4)         // 204800

typedef unsigned long long ull;

__device__ float g_WihT[NF * G4];          // [f][c]
__device__ float g_WhhT[(H + 8) * G4];     // [k][c] (+pad, now unused by ring)
__device__ float g_WoutT[H * NOUT];        // [k][oc]

// ---------------- packed f32x2 helpers ----------------
__device__ __forceinline__ void ffma2(ull& acc, ull a, ull b) {
    asm("fma.rn.f32x2 %0, %1, %2, %0;" : "+l"(acc) : "l"(a), "l"(b));
}
__device__ __forceinline__ ull pack2(float lo, float hi) {
    ull r; asm("mov.b64 %0, {%1, %2};" : "=l"(r) : "f"(lo), "f"(hi)); return r;
}
__device__ __forceinline__ void unpack2(ull v, float& lo, float& hi) {
    asm("mov.b64 {%0, %1}, %2;" : "=f"(lo), "=f"(hi) : "l"(v));
}
__device__ __forceinline__ void dup2(ull w2, ull& d0, ull& d1) {
    asm("{\n\t"
        ".reg .f32 w0, w1;\n\t"
        "mov.b64 {w0, w1}, %2;\n\t"
        "mov.b64 %0, {w0, w0};\n\t"
        "mov.b64 %1, {w1, w1};\n\t"
        "}" : "=l"(d0), "=l"(d1) : "l"(w2));
}

// ---------------- activations ----------------
__device__ __forceinline__ float ex2f(float x) { float r; asm("ex2.approx.f32 %0, %1;" : "=f"(r) : "f"(x)); return r; }
__device__ __forceinline__ float rcpf(float x) { float r; asm("rcp.approx.f32 %0, %1;" : "=f"(r) : "f"(x)); return r; }
__device__ __forceinline__ float sigmf(float x) {
    return rcpf(1.0f + ex2f(-1.4426950408889634f * x));
}
__device__ __forceinline__ float tanhf_acc(float x) {
    return fmaf(2.0f, rcpf(1.0f + ex2f(-2.8853900817779268f * x)), -1.0f);
}

// ---------------- one-time weight transpose ----------------
__global__ void prep_kernel(const float* __restrict__ W_ih,
                            const float* __restrict__ W_hh,
                            const float* __restrict__ W_out) {
    int idx = blockIdx.x * blockDim.x + threadIdx.x;
    if (idx < (NF + H) * G4) {
        int k = idx / G4;
        int c = idx - k * G4;
        if (k < NF) g_WihT[idx]               = W_ih[c * NF + k];
        else        g_WhhT[(k - NF) * G4 + c] = W_hh[c * H + (k - NF)];
    } else {
        int j = idx - (NF + H) * G4;
        if (j < H * NOUT) {
            int k = j >> 7, oc = j & 127;
            g_WoutT[k * NOUT + oc] = W_out[oc * H + k];
        }
    }
}

// row-packed micro-step
#define STEPW(W2, SRC)                                                  \
    do {                                                                \
        ull d0, d1; dup2((W2), d0, d1);                                 \
        ulonglong2 hA = *(const ulonglong2*)(SRC);                      \
        ulonglong2 hB = *(const ulonglong2*)((SRC) + 4);                \
        ffma2(q0, hA.x, d0); ffma2(q1, hA.y, d0);                       \
        ffma2(q2, hB.x, d0); ffma2(q3, hB.y, d0);                       \
        ffma2(r0, hA.x, d1); ffma2(r1, hA.y, d1);                       \
        ffma2(r2, hB.x, d1); ffma2(r3, hB.y, d1);                       \
    } while (0)

// phase-2 body: sum 4-way partials for state (hcol, prow), activate, update
#define PHASE2_BODY()                                                          \
    do {                                                                       \
        const float* pr = pf + prow * G4;                                      \
        float si = pr[hcol]                + pr[8 * G4 + hcol]                 \
                 + pr[16 * G4 + hcol]      + pr[24 * G4 + hcol];               \
        float sf = pr[hcol + 128]          + pr[8 * G4 + hcol + 128]           \
                 + pr[16 * G4 + hcol + 128] + pr[24 * G4 + hcol + 128];        \
        float sg = pr[hcol + 256]          + pr[8 * G4 + hcol + 256]           \
                 + pr[16 * G4 + hcol + 256] + pr[24 * G4 + hcol + 256];        \
        float so = pr[hcol + 384]          + pr[8 * G4 + hcol + 384]           \
                 + pr[16 * G4 + hcol + 384] + pr[24 * G4 + hcol + 384];        \
        float iv = sigmf(si), fv = sigmf(sf), gv = tanhf_acc(sg), ov = sigmf(so); \
        cs = fmaf(fv, cs, iv * gv);                                            \
        hd[hcol * M + prow] = ov * tanhf_acc(cs);                              \
    } while (0)

// ---------------- persistent fused LSTM kernel ----------------
__global__ void __launch_bounds__(NTHR, 1)
lstm_kernel(const float* __restrict__ x,
            const float* __restrict__ b_ih, const float* __restrict__ b_hh,
            const float* __restrict__ b_out,
            float* __restrict__ out)
{
    extern __shared__ float sm[];
    float* Wih = sm + OFF_WIH;
    float* xd  = sm + OFF_XD;              // [2][64][8]
    float* hd  = sm + OFF_HD;              // [128][8]
    float* pf  = sm + OFF_PART;            // [4][8][512]
    ull*   pu  = (ull*)pf;                 // [4][8][256]

    const int tid = threadIdx.x;
    const int bbase = blockIdx.x * M;

    const int cp = tid & 255;
    const int c0 = 2 * cp;
    const int kg = tid >> 8;               // 0..3

    const int xbase = kg * KX;             // x rows [xbase, xbase+16)
    const int hbase = kg * KH;             // h rows [hbase, hbase+32)

    // ---- stage Wih (coalesced) ----
    {
        const float4* s = (const float4*)g_WihT;
        float4*       d = (float4*)Wih;
        #pragma unroll
        for (int i = 0; i < (NF * G4 / 4) / NTHR; ++i) d[tid + i * NTHR] = s[tid + i * NTHR];
    }
    if (tid < H * M) hd[tid] = 0.0f;

    // x loader (tid < 512): feature lf, row lr
    const int lf = tid >> 3, lr = tid & 7;
    const float* xp = x + ((size_t)(bbase + lr) * SEQ) * NF + lf;
    if (tid < 512) xd[lf * M + lr] = xp[0];   // buffer 0, t=0

    // bias (kg0 only)
    ull bias0 = 0ull, bias1 = 0ull;
    if (kg == 0) {
        float bb0 = b_ih[c0] + b_hh[c0];
        float bb1 = b_ih[c0 + 1] + b_hh[c0 + 1];
        bias0 = pack2(bb0, bb0);
        bias1 = pack2(bb1, bb1);
    }

    // phase-2 identity (kg-private): state col hcol in [32kg,32kg+32), row prow
    const int hcol = hbase + (cp & 31);
    const int prow = cp >> 5;              // 0..7
    float cs = 0.f;

    const ull* wring0 = (const ull*)(g_WhhT + hbase * G4) + cp;

    __syncthreads();

    for (int t = 0; t < SEQ; ++t) {
        // prefetch x(t+1)
        float xpre = 0.f;
        const bool doPre = (tid < 512) && (t + 1 < SEQ);
        if (doPre) xpre = __ldg(xp + (size_t)(t + 1) * NF);

        // ring preload (consumed after named bar — long cover)
        const ull* wg = wring0;
        ull u0 = __ldg(wg + 0 * 256), u1 = __ldg(wg + 1 * 256),
            u2 = __ldg(wg + 2 * 256), u3 = __ldg(wg + 3 * 256);
        wg += 4 * 256;

        // phase 2 for step t-1: own kg's 32 h-states (hidden under x-part issue)
        if (t > 0) PHASE2_BODY();

        // accumulators
        ull q0 = bias0, q1 = bias0, q2 = bias0, q3 = bias0;
        ull r0 = bias1, r1 = bias1, r2 = bias1, r3 = bias1;

        // x-part: 16 rows, weights resident
        const float* xsb = xd + (t & 1) * (NF * M);
        #pragma unroll
        for (int j = 0; j < KX; ++j) {
            ull w2 = *(const ull*)(Wih + (xbase + j) * G4 + c0);
            STEPW(w2, xsb + (xbase + j) * M);
        }

        // kg-local barrier: own 32 hd rows complete (only this kg reads them)
        asm volatile("bar.sync %0, %1;" :: "r"(kg + 1), "n"(256) : "memory");

        // h-part: 32 streamed rows, ring-4, final group peeled (no overfetch)
        #pragma unroll
        for (int k = 0; k < KH - 4; k += 4) {
            STEPW(u0, hd + (hbase + k + 0) * M); u0 = __ldg(wg + 0 * 256);
            STEPW(u1, hd + (hbase + k + 1) * M); u1 = __ldg(wg + 1 * 256);
            STEPW(u2, hd + (hbase + k + 2) * M); u2 = __ldg(wg + 2 * 256);
            STEPW(u3, hd + (hbase + k + 3) * M); u3 = __ldg(wg + 3 * 256);
            wg += 4 * 256;
        }
        STEPW(u0, hd + (hbase + KH - 4) * M);
        STEPW(u1, hd + (hbase + KH - 3) * M);
        STEPW(u2, hd + (hbase + KH - 2) * M);
        STEPW(u3, hd + (hbase + KH - 1) * M);

        // transpose accumulators, store raw partials pf[kg][row][col]
        {
            ull* pb = pu + kg * 8 * 256 + cp;
            float x0, x1, y0, y1;
            unpack2(q0, x0, x1); unpack2(r0, y0, y1);
            pb[0 * 256] = pack2(x0, y0); pb[1 * 256] = pack2(x1, y1);
            unpack2(q1, x0, x1); unpack2(r1, y0, y1);
            pb[2 * 256] = pack2(x0, y0); pb[3 * 256] = pack2(x1, y1);
            unpack2(q2, x0, x1); unpack2(r2, y0, y1);
            pb[4 * 256] = pack2(x0, y0); pb[5 * 256] = pack2(x1, y1);
            unpack2(q3, x0, x1); unpack2(r3, y0, y1);
            pb[6 * 256] = pack2(x0, y0); pb[7 * 256] = pack2(x1, y1);
        }
        // stage x(t+1)
        if (doPre) xd[((t + 1) & 1) * (NF * M) + lf * M + lr] = xpre;

        __syncthreads();   // global: partials(t) + xd(t+1) visible
    }

    // final phase 2 (t = SEQ-1)
    PHASE2_BODY();
    __syncthreads();

    // output projection: one (row, oc) per thread
    {
        const int oc = tid & 127;
        const int rr = tid >> 7;
        float acc = b_out[oc];
        const float* wt = g_WoutT + oc;
        #pragma unroll 8
        for (int k = 0; k < H; ++k) {
            acc = fmaf(__ldg(wt + k * NOUT), hd[k * M + rr], acc);
        }
        out[(size_t)(bbase + rr) * NOUT + oc] = acc;
    }
}

extern "C" void kernel_launch(void* const* d_in, const int* in_sizes, int n_in,
                              void* d_out, int out_size)
{
    const float* x     = (const float*)d_in[0];
    const float* W_ih  = (const float*)d_in[1];
    const float* W_hh  = (const float*)d_in[2];
    const float* b_ih  = (const float*)d_in[3];
    const float* b_hh  = (const float*)d_in[4];
    const float* W_out = (const float*)d_in[5];
    const float* b_out = (const float*)d_in[6];
    float* out = (float*)d_out;

    const int prep_n = (NF + H) * G4 + H * NOUT;
    prep_kernel<<<(prep_n + 255) / 256, 256>>>(W_ih, W_hh, W_out);

    cudaFuncSetAttribute(lstm_kernel,
                         cudaFuncAttributeMaxDynamicSharedMemorySize, SMEM_BYTES);
    lstm_kernel<<<NCTA, NTHR, SMEM_BYTES>>>(x, b_ih, b_hh, b_out, out);
}